// round 1
// baseline (speedup 1.0000x reference)
#include <cuda_runtime.h>
#include <math.h>

// Shapes (fixed): B=4, S=128, D=256, H=8, HD=32, HID=256, NS=129
#define NB 4
#define SS 128
#define DD 256
#define NSQ 129
#define NH 8
#define NEGV -1000000000.0f

// ---------------- scratch (device globals; no allocation allowed) ----------
__device__ float g_t1[512 * 256];
__device__ float g_t2[512 * 256];
__device__ float g_dh[512 * 256];
__device__ float g_dt[512 * 256];
__device__ float g_nv1[512 * 256];
__device__ float g_vh[512 * 256];
__device__ float g_vt[512 * 256];
__device__ float g_Pa[512 * 256];
__device__ float g_Pb[512 * 256];
__device__ float g_q[516 * 256];
__device__ float g_k[516 * 256];
__device__ float g_v[516 * 256];
__device__ float g_G[4 * 128 * 128];
__device__ float g_adj[4 * 128 * 128];
__device__ float g_qs[4 * 8 * 129];
__device__ float g_ks[4 * 8 * 129];
__device__ float g_scores[4 * 8 * 129 * 129];
__device__ float g_ctx[516 * 256];
__device__ float g_M[256 * 8];
__device__ float g_biasE[8];

// ---------------- reduction helpers ----------------------------------------
__device__ __forceinline__ float warpSum(float v) {
#pragma unroll
    for (int o = 16; o > 0; o >>= 1) v += __shfl_xor_sync(0xffffffffu, v, o);
    return v;
}
__device__ __forceinline__ float warpMax(float v) {
#pragma unroll
    for (int o = 16; o > 0; o >>= 1) v = fmaxf(v, __shfl_xor_sync(0xffffffffu, v, o));
    return v;
}

// ---------------- generic 64x64x256 fp32 GEMM tile --------------------------
// C[M,256] = act(A[M,256] @ W[256,256] + bias)
__device__ __forceinline__ void gemm_tile(const float* __restrict__ A, int M,
                                          const float* __restrict__ W,
                                          const float* __restrict__ bias,
                                          float* __restrict__ C, int doRelu) {
    __shared__ __align__(16) float Ast[16][64];  // [k][m]
    __shared__ __align__(16) float Ws[16][64];   // [k][n]
    const int tid = threadIdx.x;  // 256 threads
    const int rowBase = blockIdx.y * 64;
    const int colBase = blockIdx.x * 64;
    if (rowBase >= M) return;
    const int tx = tid & 15, ty = tid >> 4;
    float acc[4][4] = {};
    const int aRow = tid >> 2;          // 0..63
    const int aK4 = (tid & 3) * 4;      // 0,4,8,12
    const int wK = tid >> 4;            // 0..15
    const int wC4 = (tid & 15) * 4;     // 0..60
    for (int k0 = 0; k0 < 256; k0 += 16) {
        float4 av;
        if (rowBase + aRow < M)
            av = *(const float4*)(A + (size_t)(rowBase + aRow) * 256 + k0 + aK4);
        else
            av = make_float4(0.f, 0.f, 0.f, 0.f);
        Ast[aK4 + 0][aRow] = av.x;
        Ast[aK4 + 1][aRow] = av.y;
        Ast[aK4 + 2][aRow] = av.z;
        Ast[aK4 + 3][aRow] = av.w;
        *(float4*)&Ws[wK][wC4] =
            *(const float4*)(W + (size_t)(k0 + wK) * 256 + colBase + wC4);
        __syncthreads();
#pragma unroll
        for (int kk = 0; kk < 16; kk++) {
            float4 a = *(const float4*)&Ast[kk][ty * 4];
            float4 b = *(const float4*)&Ws[kk][tx * 4];
            acc[0][0] += a.x * b.x; acc[0][1] += a.x * b.y; acc[0][2] += a.x * b.z; acc[0][3] += a.x * b.w;
            acc[1][0] += a.y * b.x; acc[1][1] += a.y * b.y; acc[1][2] += a.y * b.z; acc[1][3] += a.y * b.w;
            acc[2][0] += a.z * b.x; acc[2][1] += a.z * b.y; acc[2][2] += a.z * b.z; acc[2][3] += a.z * b.w;
            acc[3][0] += a.w * b.x; acc[3][1] += a.w * b.y; acc[3][2] += a.w * b.z; acc[3][3] += a.w * b.w;
        }
        __syncthreads();
    }
    float4 bv = bias ? *(const float4*)(bias + colBase + tx * 4)
                     : make_float4(0.f, 0.f, 0.f, 0.f);
#pragma unroll
    for (int r = 0; r < 4; r++) {
        int row = rowBase + ty * 4 + r;
        if (row < M) {
            float4 o;
            o.x = acc[r][0] + bv.x; o.y = acc[r][1] + bv.y;
            o.z = acc[r][2] + bv.z; o.w = acc[r][3] + bv.w;
            if (doRelu) {
                o.x = fmaxf(o.x, 0.f); o.y = fmaxf(o.y, 0.f);
                o.z = fmaxf(o.z, 0.f); o.w = fmaxf(o.w, 0.f);
            }
            *(float4*)(C + (size_t)row * 256 + colBase + tx * 4) = o;
        }
    }
}

// ---------------- prep: copy nv[:,1:] contiguous; fold eu_w2 @ we -----------
__global__ void prep_kernel(const float* __restrict__ nv,
                            const float* __restrict__ eu_w2,
                            const float* __restrict__ ap_w,
                            const float* __restrict__ eu_b2) {
    int tid = threadIdx.x;  // 256
    if (blockIdx.x == 0) {
        // M[c][h] = sum_t eu_w2[c][h*32+t] * we[t],  we = ap_w[64:96]
        int c = tid;
#pragma unroll
        for (int h = 0; h < 8; h++) {
            float s = 0.f;
#pragma unroll
            for (int t = 0; t < 32; t++) s += eu_w2[c * 256 + h * 32 + t] * ap_w[64 + t];
            g_M[c * 8 + h] = s;
        }
        if (tid < 8) {
            float s = 0.f;
#pragma unroll
            for (int t = 0; t < 32; t++) s += eu_b2[tid * 32 + t] * ap_w[64 + t];
            g_biasE[tid] = s;
        }
    } else {
        // copy nv[:,1:,:] -> g_nv1 (512 x 256). blocks 1..128, 4 rows each.
        int blk = blockIdx.x - 1;
        for (int r = 0; r < 4; r++) {
            int row = blk * 4 + r;            // 0..511
            int b = row >> 7, ii = row & 127;
            g_nv1[row * 256 + tid] = nv[((size_t)(b * 129 + 1 + ii)) * 256 + tid];
        }
    }
}

// ---------------- GEMM phase A: 9 independent GEMMs -------------------------
__global__ void phaseA_kernel(const float* desc, const float* nv,
                              const float* th_w1, const float* th_b1,
                              const float* tt_w1, const float* tt_b1,
                              const float* ah_w, const float* ah_b,
                              const float* at_w, const float* at_b,
                              const float* eu_w1,
                              const float* q_w, const float* q_b,
                              const float* k_w, const float* k_b,
                              const float* v_w, const float* v_b) {
    const float *A, *W, *bias;
    float* C;
    int M = 512, relu = 0;
    switch (blockIdx.z) {
        case 0: A = desc;  W = th_w1; bias = th_b1; C = g_t1; relu = 1; break;
        case 1: A = desc;  W = tt_w1; bias = tt_b1; C = g_t2; relu = 1; break;
        case 2: A = g_nv1; W = ah_w;  bias = ah_b;  C = g_vh; break;
        case 3: A = g_nv1; W = at_w;  bias = at_b;  C = g_vt; break;
        case 4: A = desc;  W = eu_w1;             bias = nullptr; C = g_Pa; break;
        case 5: A = desc;  W = eu_w1 + 256 * 256; bias = nullptr; C = g_Pb; break;
        case 6: A = nv;    W = q_w;   bias = q_b;   C = g_q; M = 516; break;
        case 7: A = nv;    W = k_w;   bias = k_b;   C = g_k; M = 516; break;
        default: A = nv;   W = v_w;   bias = v_b;   C = g_v; M = 516; break;
    }
    gemm_tile(A, M, W, bias, C, relu);
}

// ---------------- GEMM phase B: dh, dt --------------------------------------
__global__ void phaseB_kernel(const float* th_w2, const float* th_b2,
                              const float* tt_w2, const float* tt_b2) {
    if (blockIdx.z == 0)
        gemm_tile(g_t1, 512, th_w2, th_b2, g_dh, 0);
    else
        gemm_tile(g_t2, 512, tt_w2, tt_b2, g_dt, 0);
}

// ---------------- row L2-normalize dh, dt -----------------------------------
__global__ void normalize_kernel() {
    int row = blockIdx.x;  // 0..1023
    float* p = (row < 512) ? (g_dh + (size_t)row * 256)
                           : (g_dt + (size_t)(row - 512) * 256);
    int tid = threadIdx.x;  // 256
    float x = p[tid];
    __shared__ float sh[8];
    float s = warpSum(x * x);
    if ((tid & 31) == 0) sh[tid >> 5] = s;
    __syncthreads();
    float tot = sh[0] + sh[1] + sh[2] + sh[3] + sh[4] + sh[5] + sh[6] + sh[7];
    p[tid] = x / sqrtf(tot);
}

// ---------------- G = sigmoid(dh.dt^T + tb) * (vh.vt^T), diag = NEG ---------
__global__ void g_kernel(const float* __restrict__ topo) {
    int b = blockIdx.y;
    int i0 = blockIdx.x * 4;  // 32 x-blocks
    __shared__ float sdh[4][256];
    __shared__ float svh[4][256];
    int tid = threadIdx.x;  // 256
    for (int t = tid; t < 4 * 256; t += 256) {
        int ii = t >> 8, c = t & 255;
        sdh[ii][c] = g_dh[(size_t)(b * 128 + i0 + ii) * 256 + c];
        svh[ii][c] = g_vh[(size_t)(b * 128 + i0 + ii) * 256 + c];
    }
    __syncthreads();
    int w = tid >> 5, lane = tid & 31;
    float tb = topo[0];
    for (int j = w; j < 128; j += 8) {
        const float* dtp = g_dt + (size_t)(b * 128 + j) * 256;
        const float* vtp = g_vt + (size_t)(b * 128 + j) * 256;
        float da[4] = {0.f, 0.f, 0.f, 0.f}, dg[4] = {0.f, 0.f, 0.f, 0.f};
#pragma unroll
        for (int t = 0; t < 8; t++) {
            int c = lane + t * 32;
            float dv = dtp[c], vv = vtp[c];
#pragma unroll
            for (int ii = 0; ii < 4; ii++) {
                da[ii] += sdh[ii][c] * dv;
                dg[ii] += svh[ii][c] * vv;
            }
        }
#pragma unroll
        for (int o = 16; o > 0; o >>= 1) {
#pragma unroll
            for (int ii = 0; ii < 4; ii++) {
                da[ii] += __shfl_xor_sync(0xffffffffu, da[ii], o);
                dg[ii] += __shfl_xor_sync(0xffffffffu, dg[ii], o);
            }
        }
        if (lane < 4) {
            int i = i0 + lane;
            float a = 1.f / (1.f + expf(-(da[lane] + tb)));
            float gv = (i == j) ? NEGV : a * dg[lane];
            g_G[(size_t)(b * 128 + i) * 128 + j] = gv;
        }
    }
}

// ---------------- adj: thresholded renormalized softmax ---------------------
__global__ void adj_kernel(const float* __restrict__ alphap) {
    int row = blockIdx.x;  // b*128+i
    int tid = threadIdx.x;  // 128
    int w = tid >> 5, lane = tid & 31;
    float gv = g_G[(size_t)row * 128 + tid];
    __shared__ float sh[4];
    __shared__ float smx;
    float m = warpMax(gv);
    if (lane == 0) sh[w] = m;
    __syncthreads();
    if (tid == 0) smx = fmaxf(fmaxf(sh[0], sh[1]), fmaxf(sh[2], sh[3]));
    __syncthreads();
    float mx = smx;
    float alpha = fminf(fmaxf(alphap[0], 1e-5f), 1.0f);
    float thr = mx * alpha;
    float e = expf(gv - mx);
    float ek = (gv >= thr) ? e : 0.f;
    float s = warpSum(ek);
    __syncthreads();
    if (lane == 0) sh[w] = s;
    __syncthreads();
    float Z = sh[0] + sh[1] + sh[2] + sh[3];
    g_adj[(size_t)row * 128 + tid] = (Z > 0.f) ? ek / Z : 0.f;
}

// ---------------- qs[b,h,i] = q . wq ; ks = k . wk --------------------------
__global__ void qsks_kernel(const float* __restrict__ ap_w) {
    int row = blockIdx.x;  // 0..515 = b*129+i
    int b = row / 129, iN = row % 129;
    int tid = threadIdx.x;  // 256
    int h = tid >> 5, lane = tid & 31;
    float qv = g_q[(size_t)row * 256 + tid] * ap_w[lane];
    float kv = g_k[(size_t)row * 256 + tid] * ap_w[32 + lane];
    qv = warpSum(qv);
    kv = warpSum(kv);
    if (lane == 0) {
        g_qs[(size_t)(b * 8 + h) * 129 + iN] = qv;
        g_ks[(size_t)(b * 8 + h) * 129 + iN] = kv;
    }
}

// ---------------- scores: LN(Pa_i+Pb_j+b1) -> relu -> @M, assemble ----------
__global__ void scores_kernel(const float* __restrict__ eu_b1,
                              const float* __restrict__ eu_g,
                              const float* __restrict__ eu_beta,
                              const float* __restrict__ ap_b_p) {
    int i = blockIdx.x;  // 0..128
    int b = blockIdx.y;
    __shared__ float sb1[256], sg[256], sbt[256];
    __shared__ __align__(16) float sM[256 * 8];
    __shared__ float sks[8 * 129];
    __shared__ float sqs[8], sbe[8];
    int tid = threadIdx.x;  // 256
    sb1[tid] = eu_b1[tid];
    sg[tid] = eu_g[tid];
    sbt[tid] = eu_beta[tid];
    for (int t = tid; t < 2048; t += 256) sM[t] = g_M[t];
    for (int t = tid; t < 8 * 129; t += 256) sks[t] = g_ks[(size_t)b * 8 * 129 + t];
    if (tid < 8) {
        sqs[tid] = g_qs[(size_t)(b * 8 + tid) * 129 + i];
        sbe[tid] = g_biasE[tid];
    }
    __syncthreads();
    float apb = ap_b_p[0];
    int w = tid >> 5, lane = tid & 31;
    for (int j = w; j < 129; j += 8) {
        int ia = (i >= 1) ? (i - 1) : ((j >= 1) ? (j - 1) : -1);
        int ib = (j >= 1) ? (j - 1) : ((i >= 1) ? (i - 1) : -1);
        float na;
        if (i == 0) na = (j == 0) ? 0.f : 1.f;
        else        na = (j == 0) ? 0.f : g_adj[(size_t)(b * 128 + i - 1) * 128 + (j - 1)];
        int c0 = lane * 8;
        float vv[8];
        if (ia >= 0) {
            const float4* pa = (const float4*)(g_Pa + (size_t)(b * 128 + ia) * 256 + c0);
            const float4* pb = (const float4*)(g_Pb + (size_t)(b * 128 + ib) * 256 + c0);
            float4 a0 = pa[0], a1 = pa[1], b0 = pb[0], b1v = pb[1];
            vv[0] = a0.x + b0.x + sb1[c0 + 0];
            vv[1] = a0.y + b0.y + sb1[c0 + 1];
            vv[2] = a0.z + b0.z + sb1[c0 + 2];
            vv[3] = a0.w + b0.w + sb1[c0 + 3];
            vv[4] = a1.x + b1v.x + sb1[c0 + 4];
            vv[5] = a1.y + b1v.y + sb1[c0 + 5];
            vv[6] = a1.z + b1v.z + sb1[c0 + 6];
            vv[7] = a1.w + b1v.w + sb1[c0 + 7];
        } else {
#pragma unroll
            for (int u = 0; u < 8; u++) vv[u] = sb1[c0 + u];
        }
        float s = 0.f, sq = 0.f;
#pragma unroll
        for (int u = 0; u < 8; u++) { s += vv[u]; sq += vv[u] * vv[u]; }
#pragma unroll
        for (int o = 16; o > 0; o >>= 1) {
            s += __shfl_xor_sync(0xffffffffu, s, o);
            sq += __shfl_xor_sync(0xffffffffu, sq, o);
        }
        float mu = s * (1.f / 256.f);
        float var = sq * (1.f / 256.f) - mu * mu;
        float inv = rsqrtf(var + 1e-5f);
        float acc[8] = {0.f, 0.f, 0.f, 0.f, 0.f, 0.f, 0.f, 0.f};
#pragma unroll
        for (int u = 0; u < 8; u++) {
            int c = c0 + u;
            float r = (vv[u] - mu) * inv * sg[c] + sbt[c];
            r = fmaxf(r, 0.f);
            float4 m0 = *(const float4*)&sM[c * 8];
            float4 m1 = *(const float4*)&sM[c * 8 + 4];
            acc[0] += r * m0.x; acc[1] += r * m0.y; acc[2] += r * m0.z; acc[3] += r * m0.w;
            acc[4] += r * m1.x; acc[5] += r * m1.y; acc[6] += r * m1.z; acc[7] += r * m1.w;
        }
#pragma unroll
        for (int o = 16; o > 0; o >>= 1) {
#pragma unroll
            for (int hh = 0; hh < 8; hh++)
                acc[hh] += __shfl_xor_sync(0xffffffffu, acc[hh], o);
        }
        if (lane < 8) {
            int h = lane;
            float sc = sqs[h] + sks[h * 129 + j] + (acc[h] + sbe[h]) * na + apb +
                       ((na == 0.f) ? NEGV : 0.f);
            g_scores[(((size_t)(b * 8 + h) * 129 + i) * 129) + j] = sc;
        }
    }
}

// ---------------- softmax over j (129), in place; optional attn out ---------
__global__ void softmax_kernel(float* __restrict__ attn_out) {
    int row = blockIdx.x;  // (b*8+h)*129+i, 4128 rows
    float* p = g_scores + (size_t)row * 129;
    int tid = threadIdx.x;  // 128
    int w = tid >> 5, lane = tid & 31;
    float x = p[tid];
    float xt = p[128];  // everyone reads the tail element (cached)
    __shared__ float sh[4];
    __shared__ float sbc;
    float m = warpMax(fmaxf(x, xt));
    if (lane == 0) sh[w] = m;
    __syncthreads();
    if (tid == 0) sbc = fmaxf(fmaxf(sh[0], sh[1]), fmaxf(sh[2], sh[3]));
    __syncthreads();
    float mx = sbc;
    float e1 = expf(x - mx);
    float et = expf(xt - mx);
    float part = e1 + ((tid == 0) ? et : 0.f);
    float s = warpSum(part);
    __syncthreads();
    if (lane == 0) sh[w] = s;
    __syncthreads();
    float Z = sh[0] + sh[1] + sh[2] + sh[3];
    float invZ = 1.f / Z;
    p[tid] = e1 * invZ;
    if (tid == 0) p[128] = et * invZ;
    if (attn_out) {
        attn_out[(size_t)row * 129 + tid] = e1 * invZ;
        if (tid == 0) attn_out[(size_t)row * 129 + 128] = et * invZ;
    }
}

// ---------------- ctx = attn @ v --------------------------------------------
__global__ void ctx_kernel() {
    int b = blockIdx.y;
    int i0 = blockIdx.x * 4;  // 33 x-blocks cover 129
    int tid = threadIdx.x;    // 256 = channel c
    int h = tid >> 5;
    const float* vb = g_v + (size_t)b * 129 * 256;
    const float* ar[4];
#pragma unroll
    for (int ii = 0; ii < 4; ii++) {
        int irow = min(i0 + ii, 128);
        ar[ii] = g_scores + ((size_t)(b * 8 + h) * 129 + irow) * 129;
    }
    float acc[4] = {0.f, 0.f, 0.f, 0.f};
    for (int j = 0; j < 129; j++) {
        float vvv = vb[(size_t)j * 256 + tid];
#pragma unroll
        for (int ii = 0; ii < 4; ii++) acc[ii] += ar[ii][j] * vvv;
    }
#pragma unroll
    for (int ii = 0; ii < 4; ii++) {
        if (i0 + ii < 129)
            g_ctx[(size_t)(b * 129 + i0 + ii) * 256 + tid] = acc[ii];
    }
}

// ---------------- final out GEMM --------------------------------------------
__global__ void phaseC_kernel(const float* out_w, const float* out_b,
                              float* out) {
    gemm_tile(g_ctx, 516, out_w, out_b, out, 0);
}

// ---------------- launch -----------------------------------------------------
extern "C" void kernel_launch(void* const* d_in, const int* in_sizes, int n_in,
                              void* d_out, int out_size) {
    const float* desc   = (const float*)d_in[0];
    const float* nv     = (const float*)d_in[1];
    const float* th_w1  = (const float*)d_in[2];
    const float* th_b1  = (const float*)d_in[3];
    const float* th_w2  = (const float*)d_in[4];
    const float* th_b2  = (const float*)d_in[5];
    const float* tt_w1  = (const float*)d_in[6];
    const float* tt_b1  = (const float*)d_in[7];
    const float* tt_w2  = (const float*)d_in[8];
    const float* tt_b2  = (const float*)d_in[9];
    const float* ah_w   = (const float*)d_in[10];
    const float* ah_b   = (const float*)d_in[11];
    const float* at_w   = (const float*)d_in[12];
    const float* at_b   = (const float*)d_in[13];
    const float* q_w    = (const float*)d_in[14];
    const float* q_b    = (const float*)d_in[15];
    const float* k_w    = (const float*)d_in[16];
    const float* k_b    = (const float*)d_in[17];
    const float* v_w    = (const float*)d_in[18];
    const float* v_b    = (const float*)d_in[19];
    const float* eu_w1  = (const float*)d_in[20];
    const float* eu_b1  = (const float*)d_in[21];
    const float* eu_g   = (const float*)d_in[22];
    const float* eu_beta= (const float*)d_in[23];
    const float* eu_w2  = (const float*)d_in[24];
    const float* eu_b2  = (const float*)d_in[25];
    const float* ap_w   = (const float*)d_in[26];
    const float* ap_b   = (const float*)d_in[27];
    const float* out_w  = (const float*)d_in[28];
    const float* out_b  = (const float*)d_in[29];
    const float* topo   = (const float*)d_in[30];
    const float* alphap = (const float*)d_in[31];

    const int OUT_ELEMS = 4 * 129 * 256;          // 132096
    const int ATTN_ELEMS = 4 * 8 * 129 * 129;     // 532512
    float* out = (float*)d_out;
    float* attn_out = (out_size >= OUT_ELEMS + ATTN_ELEMS) ? (out + OUT_ELEMS)
                                                           : nullptr;

    prep_kernel<<<129, 256>>>(nv, eu_w2, ap_w, eu_b2);
    phaseA_kernel<<<dim3(4, 9, 9), 256>>>(desc, nv, th_w1, th_b1, tt_w1, tt_b1,
                                          ah_w, ah_b, at_w, at_b, eu_w1,
                                          q_w, q_b, k_w, k_b, v_w, v_b);
    phaseB_kernel<<<dim3(4, 8, 2), 256>>>(th_w2, th_b2, tt_w2, tt_b2);
    normalize_kernel<<<1024, 256>>>();
    g_kernel<<<dim3(32, 4), 256>>>(topo);
    adj_kernel<<<512, 128>>>(alphap);
    qsks_kernel<<<516, 256>>>(ap_w);
    scores_kernel<<<dim3(129, 4), 256>>>(eu_b1, eu_g, eu_beta, ap_b);
    softmax_kernel<<<4128, 128>>>(attn_out);
    ctx_kernel<<<dim3(33, 4), 256>>>();
    phaseC_kernel<<<dim3(4, 9, 1), 256>>>(out_w, out_b, out);
}

// round 2
// speedup vs baseline: 1.4492x; 1.4492x over previous
#include <cuda_runtime.h>
#include <math.h>

// Shapes (fixed): B=4, S=128, D=256, H=8, HD=32, HID=256, NS=129
#define NEGV -1000000000.0f

// ---------------- scratch (device globals; no allocation allowed) ----------
__device__ float g_t1[512 * 256];
__device__ float g_t2[512 * 256];
__device__ float g_dh[512 * 256];
__device__ float g_dt[512 * 256];
__device__ float g_vh[512 * 256];
__device__ float g_vt[512 * 256];
__device__ float g_Pa[512 * 256];
__device__ float g_Pb[512 * 256];
__device__ float g_q[516 * 256];
__device__ float g_k[516 * 256];
__device__ float g_v[516 * 256];
__device__ float g_adj[4 * 128 * 128];
__device__ float g_qs[4 * 8 * 129];
__device__ float g_ks[4 * 8 * 129];
__device__ float g_ctx[516 * 256];
__device__ float g_M[256 * 8];
__device__ float g_biasE[8];

// ---------------- reduction helpers ----------------------------------------
__device__ __forceinline__ float warpSum(float v) {
#pragma unroll
    for (int o = 16; o > 0; o >>= 1) v += __shfl_xor_sync(0xffffffffu, v, o);
    return v;
}
__device__ __forceinline__ float warpMax(float v) {
#pragma unroll
    for (int o = 16; o > 0; o >>= 1) v = fmaxf(v, __shfl_xor_sync(0xffffffffu, v, o));
    return v;
}

// ---------------- generic 64x64x256 fp32 GEMM tile --------------------------
// C[M,256] = act(A[M,256] @ W[256,256] + bias); srcSkip: row remap for nv[:,1:]
__device__ __forceinline__ void gemm_tile(const float* __restrict__ A, int M,
                                          const float* __restrict__ W,
                                          const float* __restrict__ bias,
                                          float* __restrict__ C, int doRelu,
                                          int srcSkip) {
    __shared__ __align__(16) float Ast[16][64];  // [k][m]
    __shared__ __align__(16) float Ws[16][64];   // [k][n]
    const int tid = threadIdx.x;  // 256 threads
    const int rowBase = blockIdx.y * 64;
    const int colBase = blockIdx.x * 64;
    if (rowBase >= M) return;
    const int tx = tid & 15, ty = tid >> 4;
    float acc[4][4] = {};
    const int aRow = tid >> 2;          // 0..63
    const int aK4 = (tid & 3) * 4;      // 0,4,8,12
    const int wK = tid >> 4;            // 0..15
    const int wC4 = (tid & 15) * 4;     // 0..60
    int row = rowBase + aRow;
    int srow = srcSkip ? (row + (row >> 7) + 1) : row;
    for (int k0 = 0; k0 < 256; k0 += 16) {
        float4 av;
        if (row < M)
            av = *(const float4*)(A + (size_t)srow * 256 + k0 + aK4);
        else
            av = make_float4(0.f, 0.f, 0.f, 0.f);
        Ast[aK4 + 0][aRow] = av.x;
        Ast[aK4 + 1][aRow] = av.y;
        Ast[aK4 + 2][aRow] = av.z;
        Ast[aK4 + 3][aRow] = av.w;
        *(float4*)&Ws[wK][wC4] =
            *(const float4*)(W + (size_t)(k0 + wK) * 256 + colBase + wC4);
        __syncthreads();
#pragma unroll
        for (int kk = 0; kk < 16; kk++) {
            float4 a = *(const float4*)&Ast[kk][ty * 4];
            float4 b = *(const float4*)&Ws[kk][tx * 4];
            acc[0][0] += a.x * b.x; acc[0][1] += a.x * b.y; acc[0][2] += a.x * b.z; acc[0][3] += a.x * b.w;
            acc[1][0] += a.y * b.x; acc[1][1] += a.y * b.y; acc[1][2] += a.y * b.z; acc[1][3] += a.y * b.w;
            acc[2][0] += a.z * b.x; acc[2][1] += a.z * b.y; acc[2][2] += a.z * b.z; acc[2][3] += a.z * b.w;
            acc[3][0] += a.w * b.x; acc[3][1] += a.w * b.y; acc[3][2] += a.w * b.z; acc[3][3] += a.w * b.w;
        }
        __syncthreads();
    }
    float4 bv = bias ? *(const float4*)(bias + colBase + tx * 4)
                     : make_float4(0.f, 0.f, 0.f, 0.f);
#pragma unroll
    for (int r = 0; r < 4; r++) {
        int orow = rowBase + ty * 4 + r;
        if (orow < M) {
            float4 o;
            o.x = acc[r][0] + bv.x; o.y = acc[r][1] + bv.y;
            o.z = acc[r][2] + bv.z; o.w = acc[r][3] + bv.w;
            if (doRelu) {
                o.x = fmaxf(o.x, 0.f); o.y = fmaxf(o.y, 0.f);
                o.z = fmaxf(o.z, 0.f); o.w = fmaxf(o.w, 0.f);
            }
            *(float4*)(C + (size_t)orow * 256 + colBase + tx * 4) = o;
        }
    }
}

// ---------------- GEMM phase A: 9 independent GEMMs -------------------------
__global__ __launch_bounds__(256) void phaseA_kernel(
    const float* desc, const float* nv,
    const float* th_w1, const float* th_b1,
    const float* tt_w1, const float* tt_b1,
    const float* ah_w, const float* ah_b,
    const float* at_w, const float* at_b,
    const float* eu_w1, const float* eu_b1,
    const float* q_w, const float* q_b,
    const float* k_w, const float* k_b,
    const float* v_w, const float* v_b) {
    const float *A, *W, *bias;
    float* C;
    int M = 512, relu = 0, skip = 0;
    switch (blockIdx.z) {
        case 0: A = desc; W = th_w1; bias = th_b1; C = g_t1; relu = 1; break;
        case 1: A = desc; W = tt_w1; bias = tt_b1; C = g_t2; relu = 1; break;
        case 2: A = nv;   W = ah_w;  bias = ah_b;  C = g_vh; skip = 1; break;
        case 3: A = nv;   W = at_w;  bias = at_b;  C = g_vt; skip = 1; break;
        case 4: A = desc; W = eu_w1;             bias = eu_b1;  C = g_Pa; break;
        case 5: A = desc; W = eu_w1 + 256 * 256; bias = nullptr; C = g_Pb; break;
        case 6: A = nv;   W = q_w;   bias = q_b;   C = g_q; M = 516; break;
        case 7: A = nv;   W = k_w;   bias = k_b;   C = g_k; M = 516; break;
        default: A = nv;  W = v_w;   bias = v_b;   C = g_v; M = 516; break;
    }
    gemm_tile(A, M, W, bias, C, relu, skip);
}

// ---------------- GEMM phase B: dh, dt --------------------------------------
__global__ __launch_bounds__(256) void phaseB_kernel(
    const float* th_w2, const float* th_b2,
    const float* tt_w2, const float* tt_b2) {
    if (blockIdx.z == 0)
        gemm_tile(g_t1, 512, th_w2, th_b2, g_dh, 0, 0);
    else
        gemm_tile(g_t2, 512, tt_w2, tt_b2, g_dt, 0, 0);
}

// ---------------- qs/ks dots + eu_w2@we fold --------------------------------
__global__ __launch_bounds__(256) void qsksM_kernel(
    const float* __restrict__ ap_w,
    const float* __restrict__ eu_w2,
    const float* __restrict__ eu_b2) {
    int tid = threadIdx.x;  // 256
    if (blockIdx.x == 516) {
        // M[c][h] = sum_t eu_w2[c][h*32+t] * we[t],  we = ap_w[64:96]
        int c = tid;
#pragma unroll
        for (int h = 0; h < 8; h++) {
            float s = 0.f;
#pragma unroll
            for (int t = 0; t < 32; t++)
                s += eu_w2[c * 256 + h * 32 + t] * ap_w[64 + t];
            g_M[c * 8 + h] = s;
        }
        if (tid < 8) {
            float s = 0.f;
#pragma unroll
            for (int t = 0; t < 32; t++) s += eu_b2[tid * 32 + t] * ap_w[64 + t];
            g_biasE[tid] = s;
        }
        return;
    }
    int row = blockIdx.x;  // 0..515 = b*129+i
    int b = row / 129, iN = row % 129;
    int h = tid >> 5, lane = tid & 31;
    float qv = g_q[(size_t)row * 256 + tid] * ap_w[lane];
    float kv = g_k[(size_t)row * 256 + tid] * ap_w[32 + lane];
    qv = warpSum(qv);
    kv = warpSum(kv);
    if (lane == 0) {
        g_qs[(size_t)(b * 8 + h) * 129 + iN] = qv;
        g_ks[(size_t)(b * 8 + h) * 129 + iN] = kv;
    }
}

// ---------------- G (norm folded) + thresholded softmax adj, fused ----------
__global__ __launch_bounds__(256) void gadj_kernel(
    const float* __restrict__ topo, const float* __restrict__ alphap) {
    int b = blockIdx.y;
    int i0 = blockIdx.x * 4;  // 32 x-blocks
    __shared__ float sdh[4][256];
    __shared__ float svh[4][256];
    __shared__ float sG[4][128];
    __shared__ float sInvI[4];
    int tid = threadIdx.x;  // 256
    for (int t = tid; t < 4 * 256; t += 256) {
        int ii = t >> 8, c = t & 255;
        sdh[ii][c] = g_dh[(size_t)(b * 128 + i0 + ii) * 256 + c];
        svh[ii][c] = g_vh[(size_t)(b * 128 + i0 + ii) * 256 + c];
    }
    __syncthreads();
    int w = tid >> 5, lane = tid & 31;
    if (w < 4) {  // dh row inverse norms
        float ss = 0.f;
#pragma unroll
        for (int t = 0; t < 8; t++) {
            float v = sdh[w][lane + t * 32];
            ss += v * v;
        }
        ss = warpSum(ss);
        if (lane == 0) sInvI[w] = rsqrtf(ss);
    }
    __syncthreads();
    float tb = topo[0];
    for (int j = w; j < 128; j += 8) {
        const float* dtp = g_dt + (size_t)(b * 128 + j) * 256;
        const float* vtp = g_vt + (size_t)(b * 128 + j) * 256;
        float da[4] = {0.f, 0.f, 0.f, 0.f}, dg[4] = {0.f, 0.f, 0.f, 0.f};
        float dss = 0.f;
#pragma unroll
        for (int t = 0; t < 8; t++) {
            int c = lane + t * 32;
            float dv = dtp[c], vv = vtp[c];
            dss += dv * dv;
#pragma unroll
            for (int ii = 0; ii < 4; ii++) {
                da[ii] += sdh[ii][c] * dv;
                dg[ii] += svh[ii][c] * vv;
            }
        }
#pragma unroll
        for (int o = 16; o > 0; o >>= 1) {
            dss += __shfl_xor_sync(0xffffffffu, dss, o);
#pragma unroll
            for (int ii = 0; ii < 4; ii++) {
                da[ii] += __shfl_xor_sync(0xffffffffu, da[ii], o);
                dg[ii] += __shfl_xor_sync(0xffffffffu, dg[ii], o);
            }
        }
        if (lane < 4) {
            int i = i0 + lane;
            float invJ = rsqrtf(dss);
            float a = 1.f / (1.f + expf(-(da[lane] * sInvI[lane] * invJ + tb)));
            sG[lane][j] = (i == j) ? NEGV : a * dg[lane];
        }
    }
    __syncthreads();
    if (w < 4) {  // adj for row i0+w
        float alpha = fminf(fmaxf(alphap[0], 1e-5f), 1.0f);
        float x[4];
#pragma unroll
        for (int q = 0; q < 4; q++) x[q] = sG[w][lane + 32 * q];
        float m = fmaxf(fmaxf(x[0], x[1]), fmaxf(x[2], x[3]));
        m = warpMax(m);
        float thr = m * alpha;
        float e[4], s = 0.f;
#pragma unroll
        for (int q = 0; q < 4; q++) {
            e[q] = (x[q] >= thr) ? expf(x[q] - m) : 0.f;
            s += e[q];
        }
        s = warpSum(s);
        float invZ = (s > 0.f) ? 1.f / s : 0.f;
        float* dst = g_adj + (size_t)(b * 128 + i0 + w) * 128;
#pragma unroll
        for (int q = 0; q < 4; q++) dst[lane + 32 * q] = e[q] * invZ;
    }
}

// ---------------- mega: scores (LN edge) + softmax + ctx, per (b,i) ---------
__global__ __launch_bounds__(256) void mega_kernel(
    const float* __restrict__ eu_g, const float* __restrict__ eu_beta,
    const float* __restrict__ ap_b_p, float* __restrict__ attn_out) {
    int i = blockIdx.x;  // 0..128
    int b = blockIdx.y;
    __shared__ float sg[256], sbt[256];
    __shared__ __align__(16) float sM[256 * 8];
    __shared__ float sks[8 * 129];
    __shared__ float sqs[8], sbe[8];
    __shared__ float sPa[256];
    __shared__ float sSc[8][132];
    int tid = threadIdx.x;  // 256
    sg[tid] = eu_g[tid];
    sbt[tid] = eu_beta[tid];
    for (int t = tid; t < 2048; t += 256) sM[t] = g_M[t];
    for (int t = tid; t < 8 * 129; t += 256) sks[t] = g_ks[(size_t)b * 8 * 129 + t];
    if (tid < 8) {
        sqs[tid] = g_qs[(size_t)(b * 8 + tid) * 129 + i];
        sbe[tid] = g_biasE[tid];
    }
    if (i >= 1) sPa[tid] = g_Pa[(size_t)(b * 128 + i - 1) * 256 + tid];
    __syncthreads();
    float apb = ap_b_p[0];
    int w = tid >> 5, lane = tid & 31;
    for (int j = w; j < 129; j += 8) {
        float na;
        if (i == 0) na = (j == 0) ? 0.f : 1.f;
        else        na = (j == 0) ? 0.f
                                  : g_adj[(size_t)(b * 128 + i - 1) * 128 + (j - 1)];
        float eterm = 0.f;
        if (na != 0.f) {  // j >= 1 guaranteed here
            int c0 = lane * 8;
            float vv[8];
            const float4* pb = (const float4*)(g_Pb + (size_t)(b * 128 + j - 1) * 256 + c0);
            float4 b0 = pb[0], b1v = pb[1];
            if (i >= 1) {
                vv[0] = sPa[c0 + 0] + b0.x;  vv[1] = sPa[c0 + 1] + b0.y;
                vv[2] = sPa[c0 + 2] + b0.z;  vv[3] = sPa[c0 + 3] + b0.w;
                vv[4] = sPa[c0 + 4] + b1v.x; vv[5] = sPa[c0 + 5] + b1v.y;
                vv[6] = sPa[c0 + 6] + b1v.z; vv[7] = sPa[c0 + 7] + b1v.w;
            } else {
                const float4* pa = (const float4*)(g_Pa + (size_t)(b * 128 + j - 1) * 256 + c0);
                float4 a0 = pa[0], a1 = pa[1];
                vv[0] = a0.x + b0.x;  vv[1] = a0.y + b0.y;
                vv[2] = a0.z + b0.z;  vv[3] = a0.w + b0.w;
                vv[4] = a1.x + b1v.x; vv[5] = a1.y + b1v.y;
                vv[6] = a1.z + b1v.z; vv[7] = a1.w + b1v.w;
            }
            float s = 0.f, sq = 0.f;
#pragma unroll
            for (int u = 0; u < 8; u++) { s += vv[u]; sq += vv[u] * vv[u]; }
#pragma unroll
            for (int o = 16; o > 0; o >>= 1) {
                s += __shfl_xor_sync(0xffffffffu, s, o);
                sq += __shfl_xor_sync(0xffffffffu, sq, o);
            }
            float mu = s * (1.f / 256.f);
            float var = sq * (1.f / 256.f) - mu * mu;
            float inv = rsqrtf(var + 1e-5f);
            float acc[8] = {0.f, 0.f, 0.f, 0.f, 0.f, 0.f, 0.f, 0.f};
#pragma unroll
            for (int u = 0; u < 8; u++) {
                int c = c0 + u;
                float r = (vv[u] - mu) * inv * sg[c] + sbt[c];
                r = fmaxf(r, 0.f);
                float4 m0 = *(const float4*)&sM[c * 8];
                float4 m1 = *(const float4*)&sM[c * 8 + 4];
                acc[0] += r * m0.x; acc[1] += r * m0.y; acc[2] += r * m0.z; acc[3] += r * m0.w;
                acc[4] += r * m1.x; acc[5] += r * m1.y; acc[6] += r * m1.z; acc[7] += r * m1.w;
            }
#pragma unroll
            for (int o = 16; o > 0; o >>= 1) {
#pragma unroll
                for (int hh = 0; hh < 8; hh++)
                    acc[hh] += __shfl_xor_sync(0xffffffffu, acc[hh], o);
            }
            if (lane < 8) eterm = acc[lane] + sbe[lane];
        }
        if (lane < 8) {
            int h = lane;
            float sc = sqs[h] + sks[h * 129 + j] + apb +
                       ((na == 0.f) ? NEGV : eterm * na);
            sSc[h][j] = sc;
        }
    }
    __syncthreads();
    // softmax per head row (warp w == head h)
    {
        int h = w;
        float x0 = sSc[h][lane], x1 = sSc[h][lane + 32];
        float x2 = sSc[h][lane + 64], x3 = sSc[h][lane + 96];
        float xt = (lane == 0) ? sSc[h][128] : NEGV;
        float m = fmaxf(fmaxf(x0, x1), fmaxf(fmaxf(x2, x3), xt));
        m = warpMax(m);
        float e0 = expf(x0 - m), e1 = expf(x1 - m);
        float e2 = expf(x2 - m), e3 = expf(x3 - m);
        float et = (lane == 0) ? expf(xt - m) : 0.f;
        float s = e0 + e1 + e2 + e3 + et;
        s = warpSum(s);
        float invZ = 1.f / s;
        sSc[h][lane] = e0 * invZ;
        sSc[h][lane + 32] = e1 * invZ;
        sSc[h][lane + 64] = e2 * invZ;
        sSc[h][lane + 96] = e3 * invZ;
        if (lane == 0) sSc[h][128] = et * invZ;
        if (attn_out) {
            float* ap = attn_out + ((size_t)(b * 8 + h) * 129 + i) * 129;
            ap[lane] = e0 * invZ;
            ap[lane + 32] = e1 * invZ;
            ap[lane + 64] = e2 * invZ;
            ap[lane + 96] = e3 * invZ;
            if (lane == 0) ap[128] = et * invZ;
        }
    }
    __syncthreads();
    // ctx: warp h computes channels h*32+lane
    {
        int h = w;
        const float* vbase = g_v + (size_t)b * 129 * 256 + h * 32 + lane;
        float acc = 0.f;
#pragma unroll 4
        for (int j = 0; j < 128; j += 4) {
            acc += sSc[h][j + 0] * vbase[(size_t)(j + 0) * 256];
            acc += sSc[h][j + 1] * vbase[(size_t)(j + 1) * 256];
            acc += sSc[h][j + 2] * vbase[(size_t)(j + 2) * 256];
            acc += sSc[h][j + 3] * vbase[(size_t)(j + 3) * 256];
        }
        acc += sSc[h][128] * vbase[(size_t)128 * 256];
        g_ctx[(size_t)(b * 129 + i) * 256 + h * 32 + lane] = acc;
    }
}

// ---------------- final out GEMM --------------------------------------------
__global__ __launch_bounds__(256) void phaseC_kernel(const float* out_w,
                                                     const float* out_b,
                                                     float* out) {
    gemm_tile(g_ctx, 516, out_w, out_b, out, 0, 0);
}

// ---------------- launch -----------------------------------------------------
extern "C" void kernel_launch(void* const* d_in, const int* in_sizes, int n_in,
                              void* d_out, int out_size) {
    const float* desc   = (const float*)d_in[0];
    const float* nv     = (const float*)d_in[1];
    const float* th_w1  = (const float*)d_in[2];
    const float* th_b1  = (const float*)d_in[3];
    const float* th_w2  = (const float*)d_in[4];
    const float* th_b2  = (const float*)d_in[5];
    const float* tt_w1  = (const float*)d_in[6];
    const float* tt_b1  = (const float*)d_in[7];
    const float* tt_w2  = (const float*)d_in[8];
    const float* tt_b2  = (const float*)d_in[9];
    const float* ah_w   = (const float*)d_in[10];
    const float* ah_b   = (const float*)d_in[11];
    const float* at_w   = (const float*)d_in[12];
    const float* at_b   = (const float*)d_in[13];
    const float* q_w    = (const float*)d_in[14];
    const float* q_b    = (const float*)d_in[15];
    const float* k_w    = (const float*)d_in[16];
    const float* k_b    = (const float*)d_in[17];
    const float* v_w    = (const float*)d_in[18];
    const float* v_b    = (const float*)d_in[19];
    const float* eu_w1  = (const float*)d_in[20];
    const float* eu_b1  = (const float*)d_in[21];
    const float* eu_g   = (const float*)d_in[22];
    const float* eu_beta= (const float*)d_in[23];
    const float* eu_w2  = (const float*)d_in[24];
    const float* eu_b2  = (const float*)d_in[25];
    const float* ap_w   = (const float*)d_in[26];
    const float* ap_b   = (const float*)d_in[27];
    const float* out_w  = (const float*)d_in[28];
    const float* out_b  = (const float*)d_in[29];
    const float* topo   = (const float*)d_in[30];
    const float* alphap = (const float*)d_in[31];

    const int OUT_ELEMS = 4 * 129 * 256;          // 132096
    const int ATTN_ELEMS = 4 * 8 * 129 * 129;     // 532512
    float* out = (float*)d_out;
    float* attn_out = (out_size >= OUT_ELEMS + ATTN_ELEMS) ? (out + OUT_ELEMS)
                                                           : nullptr;

    phaseA_kernel<<<dim3(4, 9, 9), 256>>>(desc, nv, th_w1, th_b1, tt_w1, tt_b1,
                                          ah_w, ah_b, at_w, at_b, eu_w1, eu_b1,
                                          q_w, q_b, k_w, k_b, v_w, v_b);
    qsksM_kernel<<<517, 256>>>(ap_w, eu_w2, eu_b2);
    phaseB_kernel<<<dim3(4, 8, 2), 256>>>(th_w2, th_b2, tt_w2, tt_b2);
    gadj_kernel<<<dim3(32, 4), 256>>>(topo, alphap);
    mega_kernel<<<dim3(129, 4), 256>>>(eu_g, eu_beta, ap_b, attn_out);
    phaseC_kernel<<<dim3(4, 9, 1), 256>>>(out_w, out_b, out);
}